// round 5
// baseline (speedup 1.0000x reference)
#include <cuda_runtime.h>
#include <cstdint>

#define THREADS 256

namespace {
constexpr int H_   = 16;
constexpr int N_   = 4096;
constexpr int D_   = 128;
constexpr int CHK  = 128;
constexpr int NBLK = 32;
constexpr int BHc  = 32;
constexpr int NCTA = 1024;

constexpr int ST   = 136;            // tile row stride (8 mod 32 -> LDS.64 conflict-free)
constexpr int STG  = 129;            // stage stride (1 mod 32 -> column ops conflict-light)
constexpr int BUFN   = ST * 128;     // 17408 floats per tile
constexpr int STAGEN = STG * 128;    // 16512 floats

// smem float-index offsets
constexpr int F_TAB = 0;             // 128 floats
constexpr int F_A   = 128;           // tile A (q / vT). In out_kernel also v-stage.
constexpr int F_B   = F_A + BUFN;    // tile B (k -> S -> vT | kT)
constexpr int F_C   = F_B + BUFN;    // kdv: stage; out: scores tile

constexpr int SMEM_KDV = (F_C + STAGEN) * 4;   // 205824 B
constexpr int SMEM_OUT = (F_C + BUFN) * 4;     // 209408 B
}

__device__ float g_states[(size_t)NCTA * D_ * D_];

// ---------------------------------------------------------------------------
__device__ __forceinline__ uint32_t f2tf(float x) {
    uint32_t u;
    asm("cvt.rna.tf32.f32 %0, %1;" : "=r"(u) : "f"(x));
    return u;
}

// D += A*B ; m16n8k8 tf32
__device__ __forceinline__ void mma8(float* d, const uint32_t* a, const uint32_t* b) {
    asm volatile(
        "mma.sync.aligned.m16n8k8.row.col.f32.tf32.tf32.f32 "
        "{%0,%1,%2,%3}, {%4,%5,%6,%7}, {%8,%9}, {%0,%1,%2,%3};"
        : "+f"(d[0]), "+f"(d[1]), "+f"(d[2]), "+f"(d[3])
        : "r"(a[0]), "r"(a[1]), "r"(a[2]), "r"(a[3]), "r"(b[0]), "r"(b[1]));
}

// Paired fragment loads: thread (g = lane>>2, c = lane&3) owns physical k
// columns (k0+2c, k0+2c+1) in slots (·,·+4). Valid because A and B share the
// same physical-k relabel (reduction order-independent).
__device__ __forceinline__ void fragA(const float* T, int m0, int k0, int g, int c, uint32_t* a) {
    float2 x = *reinterpret_cast<const float2*>(T + (m0 + g) * ST + k0 + 2 * c);
    float2 y = *reinterpret_cast<const float2*>(T + (m0 + g + 8) * ST + k0 + 2 * c);
    a[0] = __float_as_uint(x.x); a[2] = __float_as_uint(x.y);
    a[1] = __float_as_uint(y.x); a[3] = __float_as_uint(y.y);
}
__device__ __forceinline__ void fragB(const float* T, int n0, int k0, int g, int c, uint32_t* b) {
    float2 z = *reinterpret_cast<const float2*>(T + (n0 + g) * ST + k0 + 2 * c);
    b[0] = __float_as_uint(z.x); b[1] = __float_as_uint(z.y);
}

// gmem fp32 [r][c] (128x128) -> smem tf32 K-major [r][c] stride ST (float4 path)
__device__ __forceinline__ void load_nat(const float* __restrict__ src, float* dst) {
    #pragma unroll 4
    for (int i = threadIdx.x; i < 128 * 32; i += THREADS) {
        int r = i >> 5, c4 = (i & 31) << 2;
        float4 f = *reinterpret_cast<const float4*>(src + r * 128 + c4);
        float4 w;
        w.x = __uint_as_float(f2tf(f.x));
        w.y = __uint_as_float(f2tf(f.y));
        w.z = __uint_as_float(f2tf(f.z));
        w.w = __uint_as_float(f2tf(f.w));
        *reinterpret_cast<float4*>(dst + r * ST + c4) = w;
    }
}

// gmem [s][e] -> stage[e][s] (stride STG), optional per-s scale (fp32 kept)
__device__ __forceinline__ void stage_T(const float* __restrict__ src, float* stg,
                                        const float* rowscale) {
    #pragma unroll 4
    for (int i = threadIdx.x; i < 128 * 32; i += THREADS) {
        int s = i >> 5, e4 = (i & 31) << 2;
        float4 f = *reinterpret_cast<const float4*>(src + s * 128 + e4);
        float sc = rowscale ? rowscale[s] : 1.0f;
        stg[(e4 + 0) * STG + s] = f.x * sc;
        stg[(e4 + 1) * STG + s] = f.y * sc;
        stg[(e4 + 2) * STG + s] = f.z * sc;
        stg[(e4 + 3) * STG + s] = f.w * sc;
    }
}

// stage[e][s] -> tile[e][s] stride ST, cvt tf32 (vectorized writes)
__device__ __forceinline__ void tile_from_stage(const float* stg, float* dst) {
    #pragma unroll 4
    for (int i = threadIdx.x; i < 128 * 32; i += THREADS) {
        int e = i >> 5, s4 = (i & 31) << 2;
        const float* p = stg + e * STG + s4;
        float4 w;
        w.x = __uint_as_float(f2tf(p[0]));
        w.y = __uint_as_float(f2tf(p[1]));
        w.z = __uint_as_float(f2tf(p[2]));
        w.w = __uint_as_float(f2tf(p[3]));
        *reinterpret_cast<float4*>(dst + e * ST + s4) = w;
    }
}

// 128x128x128 GEMM, both operands K-major, double-buffered fragment pipeline.
__device__ __forceinline__ void gemm128(const float* A, const float* B,
                                        float acc[2][8][4], int m0w, int n0w,
                                        int g, int c) {
    uint32_t af[2][2][4];
    uint32_t bf[2][8][2];
    // prologue: k-step 0
    fragA(A, m0w,      0, g, c, af[0][0]);
    fragA(A, m0w + 16, 0, g, c, af[0][1]);
    #pragma unroll
    for (int nt = 0; nt < 8; nt++) fragB(B, n0w + nt * 8, 0, g, c, bf[0][nt]);

    #pragma unroll
    for (int ks = 0; ks < 16; ks++) {
        const int cur = ks & 1, nxt = cur ^ 1;
        if (ks < 15) {
            const int k0 = (ks + 1) * 8;
            fragA(A, m0w,      k0, g, c, af[nxt][0]);
            fragA(A, m0w + 16, k0, g, c, af[nxt][1]);
            #pragma unroll
            for (int nt = 0; nt < 8; nt++) fragB(B, n0w + nt * 8, k0, g, c, bf[nxt][nt]);
        }
        #pragma unroll
        for (int nt = 0; nt < 8; nt++) {
            mma8(acc[0][nt], af[cur][0], bf[cur][nt]);
            mma8(acc[1][nt], af[cur][1], bf[cur][nt]);
        }
    }
}

__device__ __forceinline__ void zero_acc(float acc[2][8][4]) {
    #pragma unroll
    for (int mt = 0; mt < 2; mt++)
        #pragma unroll
        for (int nt = 0; nt < 8; nt++)
            #pragma unroll
            for (int r = 0; r < 4; r++) acc[mt][nt][r] = 0.f;
}

// ---------------------------------------------------------------------------
// Kernel 1: g_states[bhc][e][d] = sum_s v[s][e] * k[s][d] * exp(-sl*(CHK-s))
// Both operands transposed to K-major (k = s) through the stage.
// ---------------------------------------------------------------------------
__global__ void __launch_bounds__(THREADS, 1)
kdv_kernel(const float* __restrict__ k_g, const float* __restrict__ v_g,
           const float* __restrict__ s_g)
{
    extern __shared__ float sm[];
    float* tab  = sm + F_TAB;
    float* bufV = sm + F_A;     // vT [e][s] K-major
    float* bufK = sm + F_B;     // kT [d][s] K-major, scaled by kdec[s]
    float* stg  = sm + F_C;

    const int tid = threadIdx.x;
    const int bhc = blockIdx.x;
    const int bh = bhc >> 5, h = bh & (H_ - 1);
    const float sl = s_g[h];
    const size_t cbase = ((size_t)bh * N_ + (size_t)(bhc & 31) * CHK) * D_;

    if (tid < 128) tab[tid] = expf(-sl * (float)(CHK - tid));
    __syncthreads();

    stage_T(k_g + cbase, stg, tab);
    __syncthreads();
    tile_from_stage(stg, bufK);
    __syncthreads();
    stage_T(v_g + cbase, stg, nullptr);
    __syncthreads();
    tile_from_stage(stg, bufV);
    __syncthreads();

    const int lane = tid & 31, wid = tid >> 5;
    const int g = lane >> 2, c = lane & 3;
    const int m0w = (wid & 3) * 32, n0w = (wid >> 2) * 64;

    float acc[2][8][4];
    zero_acc(acc);
    gemm128(bufV, bufK, acc, m0w, n0w, g, c);   // A=vT (m=e), B=kT (n=d)

    float* outp = g_states + (size_t)bhc * D_ * D_;
    #pragma unroll
    for (int mt = 0; mt < 2; mt++) {
        int r0 = m0w + mt * 16 + g;
        #pragma unroll
        for (int nt = 0; nt < 8; nt++) {
            int col = n0w + nt * 8 + 2 * c;
            *reinterpret_cast<float2*>(outp + r0 * 128 + col) =
                make_float2(acc[mt][nt][0], acc[mt][nt][1]);
            *reinterpret_cast<float2*>(outp + (r0 + 8) * 128 + col) =
                make_float2(acc[mt][nt][2], acc[mt][nt][3]);
        }
    }
}

// ---------------------------------------------------------------------------
// Kernel 2: exclusive decay scan over chunks (elementwise on [e][d] states)
// ---------------------------------------------------------------------------
__global__ void __launch_bounds__(THREADS, 1)
scan_kernel(const float* __restrict__ s_g)
{
    const int bh  = blockIdx.x >> 3;
    const int sli = blockIdx.x & 7;
    const int h   = bh & (H_ - 1);
    const float bd = expf(-s_g[h] * (float)CHK);
    const int tid = threadIdx.x;

    int u0 = tid,       d0 = u0 >> 2, q0 = u0 & 3;
    int u1 = tid + 256, d1 = u1 >> 2, q1 = u1 & 3;
    const int off0 = d0 * 32 + sli * 4 + q0;
    const int off1 = d1 * 32 + sli * 4 + q1;

    float4* base = reinterpret_cast<float4*>(g_states) + (size_t)bh * NBLK * (D_ * D_ / 4);
    float4 r0 = make_float4(0.f, 0.f, 0.f, 0.f), r1 = r0;
    for (int cc = 0; cc < NBLK; cc++) {
        float4* p = base + (size_t)cc * (D_ * D_ / 4);
        float4 t0 = p[off0], t1 = p[off1];
        p[off0] = r0;  p[off1] = r1;
        r0.x = bd * r0.x + t0.x;  r0.y = bd * r0.y + t0.y;
        r0.z = bd * r0.z + t0.z;  r0.w = bd * r0.w + t0.w;
        r1.x = bd * r1.x + t1.x;  r1.y = bd * r1.y + t1.y;
        r1.z = bd * r1.z + t1.z;  r1.w = bd * r1.w + t1.w;
    }
}

// ---------------------------------------------------------------------------
// Kernel 3: per (b,h,chunk):
//   GEMM1: sc[t][s] = mask(t>=s) * exp(-sl(t-s)) * (q . k)
//   GEMM2: o  = exp(-sl t) * (q @ S)    (S stored [e][d] -> K-major)
//   GEMM3: o += sc @ vT                 (v transposed in-kernel -> K-major)
// ---------------------------------------------------------------------------
__global__ void __launch_bounds__(THREADS, 1)
out_kernel(const float* __restrict__ q_g, const float* __restrict__ k_g,
           const float* __restrict__ v_g, const float* __restrict__ s_g,
           float* __restrict__ o_g)
{
    extern __shared__ float sm[];
    float* tab  = sm + F_TAB;
    float* bufQ = sm + F_A;     // q [t][d]; later reused as v stage
    float* bufB = sm + F_B;     // k -> S -> vT
    float* bufS = sm + F_C;     // scores [t][s]

    const int tid = threadIdx.x;
    const int bhc = blockIdx.x;
    const int bh = bhc >> 5, h = bh & (H_ - 1);
    const float sl = s_g[h];
    const size_t cbase = ((size_t)bh * N_ + (size_t)(bhc & 31) * CHK) * D_;

    if (tid < 128) tab[tid] = expf(-sl * (float)tid);

    load_nat(q_g + cbase, bufQ);
    load_nat(k_g + cbase, bufB);
    __syncthreads();

    const int lane = tid & 31, wid = tid >> 5;
    const int g = lane >> 2, c = lane & 3;
    const int m0w = (wid & 3) * 32, n0w = (wid >> 2) * 64;

    float acc[2][8][4];
    zero_acc(acc);

    // GEMM1: scores = q . k^T
    gemm128(bufQ, bufB, acc, m0w, n0w, g, c);
    __syncthreads();                               // k reads done

    // transform -> bufS (mask + decay + tf32), zero acc; overlap: load S -> bufB
    #pragma unroll
    for (int mt = 0; mt < 2; mt++) {
        int t0 = m0w + mt * 16 + g, t1 = t0 + 8;
        #pragma unroll
        for (int nt = 0; nt < 8; nt++) {
            int s0 = n0w + nt * 8 + 2 * c;
            float w00 = (t0 >= s0)     ? acc[mt][nt][0] * tab[t0 - s0]     : 0.f;
            float w01 = (t0 >= s0 + 1) ? acc[mt][nt][1] * tab[t0 - s0 - 1] : 0.f;
            float w10 = (t1 >= s0)     ? acc[mt][nt][2] * tab[t1 - s0]     : 0.f;
            float w11 = (t1 >= s0 + 1) ? acc[mt][nt][3] * tab[t1 - s0 - 1] : 0.f;
            bufS[t0 * ST + s0]     = __uint_as_float(f2tf(w00));
            bufS[t0 * ST + s0 + 1] = __uint_as_float(f2tf(w01));
            bufS[t1 * ST + s0]     = __uint_as_float(f2tf(w10));
            bufS[t1 * ST + s0 + 1] = __uint_as_float(f2tf(w11));
            acc[mt][nt][0] = acc[mt][nt][1] = acc[mt][nt][2] = acc[mt][nt][3] = 0.f;
        }
    }
    load_nat(g_states + (size_t)bhc * D_ * D_, bufB);
    __syncthreads();                               // S ready + bufS written

    // GEMM2: inter = q @ S  (S[e][d]: n=e, k=d)
    gemm128(bufQ, bufB, acc, m0w, n0w, g, c);

    // scale inter rows by exp(-sl*t)
    #pragma unroll
    for (int mt = 0; mt < 2; mt++) {
        float f0 = tab[m0w + mt * 16 + g];
        float f1 = tab[m0w + mt * 16 + g + 8];
        #pragma unroll
        for (int nt = 0; nt < 8; nt++) {
            acc[mt][nt][0] *= f0;  acc[mt][nt][1] *= f0;
            acc[mt][nt][2] *= f1;  acc[mt][nt][3] *= f1;
        }
    }
    __syncthreads();                               // q + S reads done

    // v -> transpose via stage (in dead bufQ) -> bufB as vT [e][s] K-major
    stage_T(v_g + cbase, bufQ, nullptr);
    __syncthreads();
    tile_from_stage(bufQ, bufB);
    __syncthreads();

    // GEMM3: o += sc @ vT  (sc K-major [t][s]; vT K-major [e][s])
    gemm128(bufS, bufB, acc, m0w, n0w, g, c);

    float* oc = o_g + cbase;
    #pragma unroll
    for (int mt = 0; mt < 2; mt++) {
        int r0 = m0w + mt * 16 + g;
        #pragma unroll
        for (int nt = 0; nt < 8; nt++) {
            int col = n0w + nt * 8 + 2 * c;
            *reinterpret_cast<float2*>(oc + r0 * 128 + col) =
                make_float2(acc[mt][nt][0], acc[mt][nt][1]);
            *reinterpret_cast<float2*>(oc + (r0 + 8) * 128 + col) =
                make_float2(acc[mt][nt][2], acc[mt][nt][3]);
        }
    }
}

// ---------------------------------------------------------------------------
extern "C" void kernel_launch(void* const* d_in, const int* in_sizes, int n_in,
                              void* d_out, int out_size)
{
    const float* q = (const float*)d_in[0];
    const float* k = (const float*)d_in[1];
    const float* v = (const float*)d_in[2];
    const float* s = (const float*)d_in[3];
    float* o = (float*)d_out;

    cudaFuncSetAttribute(kdv_kernel, cudaFuncAttributeMaxDynamicSharedMemorySize, SMEM_KDV);
    cudaFuncSetAttribute(out_kernel, cudaFuncAttributeMaxDynamicSharedMemorySize, SMEM_OUT);

    kdv_kernel<<<NCTA, THREADS, SMEM_KDV>>>(k, v, s);
    scan_kernel<<<BHc * 8, THREADS>>>(s);
    out_kernel<<<NCTA, THREADS, SMEM_OUT>>>(q, k, v, s, o);
}

// round 6
// speedup vs baseline: 1.3516x; 1.3516x over previous
#include <cuda_runtime.h>
#include <cstdint>

#define THREADS 256

namespace {
constexpr int H_   = 16;
constexpr int N_   = 4096;
constexpr int D_   = 128;
constexpr int CHK  = 128;
constexpr int NBLK = 32;
constexpr int BHc  = 32;
constexpr int NCTA = 1024;

constexpr int STT = 132;   // transposed-storage stride ([k][m]); lane addr 4c+g -> conflict-free
constexpr int STK = 36;    // K-major chunk stride ([m][k], 32 k + pad4); lane addr 4g+c -> conflict-free
constexpr int STS_ = 132;  // scores stride (K-major, full 128 k)

// kdv smem (floats)
constexpr int KF_TAB = 0;
constexpr int KF_V   = 128;                 // [32][STT]
constexpr int KF_K   = KF_V + 32 * STT;     // [32][STT]
constexpr int SMEM_KDV = (KF_K + 32 * STT) * 4;        // 34,304 B

// out smem (floats)
constexpr int OF_TAB = 0;
constexpr int OF_SC  = 128;                 // scores [128][STS_]
constexpr int OF_S1  = OF_SC + 128 * STS_;  // stream buf 1 [128][STK]  (q)
constexpr int OF_S2  = OF_S1 + 128 * STK;   // stream buf 2 [128][STK]  (k/S) ; phase3: v [32][STT]
constexpr int SMEM_OUT = (OF_S2 + 128 * STK) * 4;      // 104,960 B
}

__device__ float g_states[(size_t)NCTA * D_ * D_];

// ---------------------------------------------------------------------------
__device__ __forceinline__ uint32_t f2tf(float x) {
    uint32_t u;
    asm("cvt.rna.tf32.f32 %0, %1;" : "=r"(u) : "f"(x));
    return u;
}

__device__ __forceinline__ void mma8(float* d, const uint32_t* a, const uint32_t* b) {
    asm volatile(
        "mma.sync.aligned.m16n8k8.row.col.f32.tf32.tf32.f32 "
        "{%0,%1,%2,%3}, {%4,%5,%6,%7}, {%8,%9}, {%0,%1,%2,%3};"
        : "+f"(d[0]), "+f"(d[1]), "+f"(d[2]), "+f"(d[3])
        : "r"(a[0]), "r"(a[1]), "r"(a[2]), "r"(a[3]), "r"(b[0]), "r"(b[1]));
}

// ---- fragment loaders (g = lane>>2, c = lane&3) ----
// K-major tile T[row][k], stride st:
__device__ __forceinline__ void fragA_K(const float* T, int st, int m0, int k0, int g, int c, uint32_t* a) {
    const float* p = T + (m0 + g) * st + k0 + c;
    a[0] = __float_as_uint(p[0]);
    a[2] = __float_as_uint(p[4]);
    p += 8 * st;
    a[1] = __float_as_uint(p[0]);
    a[3] = __float_as_uint(p[4]);
}
__device__ __forceinline__ void fragB_K(const float* T, int st, int n0, int k0, int g, int c, uint32_t* b) {
    const float* p = T + (n0 + g) * st + k0 + c;
    b[0] = __float_as_uint(p[0]);
    b[1] = __float_as_uint(p[4]);
}
// transposed storage T[k][m], stride STT:
__device__ __forceinline__ void fragA_T(const float* T, int m0, int k0, int g, int c, uint32_t* a) {
    const float* p = T + (k0 + c) * STT + m0 + g;
    a[0] = __float_as_uint(p[0]);
    a[1] = __float_as_uint(p[8]);
    p += 4 * STT;
    a[2] = __float_as_uint(p[0]);
    a[3] = __float_as_uint(p[8]);
}
__device__ __forceinline__ void fragB_T(const float* T, int n0, int k0, int g, int c, uint32_t* b) {
    const float* p = T + (k0 + c) * STT + n0 + g;
    b[0] = __float_as_uint(p[0]);
    b[1] = __float_as_uint(p[4 * STT]);
}

// ---- 32-wide-k chunk GEMMs (acc += A*B over 4 k-steps) ----
// both K-major chunks, local k:
__device__ __forceinline__ void gemm_chunk_KK(const float* A, const float* B,
                                              float acc[2][8][4], int m0w, int n0w,
                                              int g, int c) {
    #pragma unroll
    for (int ks = 0; ks < 4; ks++) {
        const int k0 = ks * 8;
        uint32_t af[2][4];
        fragA_K(A, STK, m0w,      k0, g, c, af[0]);
        fragA_K(A, STK, m0w + 16, k0, g, c, af[1]);
        #pragma unroll
        for (int nt = 0; nt < 8; nt++) {
            uint32_t bf[2];
            fragB_K(B, STK, n0w + nt * 8, k0, g, c, bf);
            mma8(acc[0][nt], af[0], bf);
            mma8(acc[1][nt], af[1], bf);
        }
    }
}
// both transposed chunks, local k:
__device__ __forceinline__ void gemm_chunk_TT(const float* A, const float* B,
                                              float acc[2][8][4], int m0w, int n0w,
                                              int g, int c) {
    #pragma unroll
    for (int ks = 0; ks < 4; ks++) {
        const int k0 = ks * 8;
        uint32_t af[2][4];
        fragA_T(A, m0w,      k0, g, c, af[0]);
        fragA_T(A, m0w + 16, k0, g, c, af[1]);
        #pragma unroll
        for (int nt = 0; nt < 8; nt++) {
            uint32_t bf[2];
            fragB_T(B, n0w + nt * 8, k0, g, c, bf);
            mma8(acc[0][nt], af[0], bf);
            mma8(acc[1][nt], af[1], bf);
        }
    }
}
// A = full K-major scores (stride STS_, global k = kbase+local), B transposed chunk:
__device__ __forceinline__ void gemm_chunk_ST(const float* A, const float* B, int kbase,
                                              float acc[2][8][4], int m0w, int n0w,
                                              int g, int c) {
    #pragma unroll
    for (int ks = 0; ks < 4; ks++) {
        const int k0 = ks * 8;
        uint32_t af[2][4];
        fragA_K(A, STS_, m0w,      kbase + k0, g, c, af[0]);
        fragA_K(A, STS_, m0w + 16, kbase + k0, g, c, af[1]);
        #pragma unroll
        for (int nt = 0; nt < 8; nt++) {
            uint32_t bf[2];
            fragB_T(B, n0w + nt * 8, k0, g, c, bf);
            mma8(acc[0][nt], af[0], bf);
            mma8(acc[1][nt], af[1], bf);
        }
    }
}

__device__ __forceinline__ void zero_acc(float acc[2][8][4]) {
    #pragma unroll
    for (int mt = 0; mt < 2; mt++)
        #pragma unroll
        for (int nt = 0; nt < 8; nt++)
            #pragma unroll
            for (int r = 0; r < 4; r++) acc[mt][nt][r] = 0.f;
}

// ---- chunk loaders (256 threads) ----
// gmem [128 rows][128] cols [dc*32, dc*32+32) -> K-major chunk [128][STK]
__device__ __forceinline__ void load_kchunk(const float* __restrict__ src, int dc, float* dst) {
    #pragma unroll
    for (int it = 0; it < 4; it++) {
        int i = threadIdx.x + it * THREADS;        // 1024 float4 slots
        int r = i >> 3, c4 = (i & 7) << 2;
        float4 f = *reinterpret_cast<const float4*>(src + r * 128 + dc * 32 + c4);
        float4 w;
        w.x = __uint_as_float(f2tf(f.x));
        w.y = __uint_as_float(f2tf(f.y));
        w.z = __uint_as_float(f2tf(f.z));
        w.w = __uint_as_float(f2tf(f.w));
        *reinterpret_cast<float4*>(dst + r * STK + c4) = w;
    }
}
// gmem rows [sc*32, sc*32+32) x 128 cols -> transposed-storage chunk [32][STT]
// (row-major copy; "transposed" only in how frags index it). optional per-row scale.
__device__ __forceinline__ void load_tchunk(const float* __restrict__ src, int sc, float* dst,
                                            const float* rowscale) {
    #pragma unroll
    for (int it = 0; it < 4; it++) {
        int i = threadIdx.x + it * THREADS;        // 1024 float4 slots
        int r = i >> 5, c4 = (i & 31) << 2;
        float4 f = *reinterpret_cast<const float4*>(src + (sc * 32 + r) * 128 + c4);
        float s = rowscale ? rowscale[sc * 32 + r] : 1.0f;
        float4 w;
        w.x = __uint_as_float(f2tf(f.x * s));
        w.y = __uint_as_float(f2tf(f.y * s));
        w.z = __uint_as_float(f2tf(f.z * s));
        w.w = __uint_as_float(f2tf(f.w * s));
        *reinterpret_cast<float4*>(dst + r * STT + c4) = w;
    }
}

// ---------------------------------------------------------------------------
// Kernel 1: g_states[bhc][e][d] = sum_s v[s][e] * k[s][d] * exp(-sl*(CHK-s))
// s streamed in 4 chunks of 32.
// ---------------------------------------------------------------------------
__global__ void __launch_bounds__(THREADS, 2)
kdv_kernel(const float* __restrict__ k_g, const float* __restrict__ v_g,
           const float* __restrict__ s_g)
{
    extern __shared__ float sm[];
    float* tab  = sm + KF_TAB;
    float* bufV = sm + KF_V;
    float* bufK = sm + KF_K;

    const int tid = threadIdx.x;
    const int bhc = blockIdx.x;
    const int bh = bhc >> 5, h = bh & (H_ - 1);
    const float sl = s_g[h];
    const size_t cbase = ((size_t)bh * N_ + (size_t)(bhc & 31) * CHK) * D_;

    if (tid < 128) tab[tid] = expf(-sl * (float)(CHK - tid));
    __syncthreads();

    const int lane = tid & 31, wid = tid >> 5;
    const int g = lane >> 2, c = lane & 3;
    const int m0w = (wid & 3) * 32, n0w = (wid >> 2) * 64;

    float acc[2][8][4];
    zero_acc(acc);

    #pragma unroll 1
    for (int sc = 0; sc < 4; sc++) {
        load_tchunk(v_g + cbase, sc, bufV, nullptr);
        load_tchunk(k_g + cbase, sc, bufK, tab);
        __syncthreads();
        gemm_chunk_TT(bufV, bufK, acc, m0w, n0w, g, c);   // A=v (m=e), B=k (n=d)
        __syncthreads();
    }

    float* outp = g_states + (size_t)bhc * D_ * D_;
    #pragma unroll
    for (int mt = 0; mt < 2; mt++) {
        int r0 = m0w + mt * 16 + g;
        #pragma unroll
        for (int nt = 0; nt < 8; nt++) {
            int col = n0w + nt * 8 + 2 * c;
            *reinterpret_cast<float2*>(outp + r0 * 128 + col) =
                make_float2(acc[mt][nt][0], acc[mt][nt][1]);
            *reinterpret_cast<float2*>(outp + (r0 + 8) * 128 + col) =
                make_float2(acc[mt][nt][2], acc[mt][nt][3]);
        }
    }
}

// ---------------------------------------------------------------------------
// Kernel 2: exclusive decay scan over chunks (elementwise on [e][d] states)
// ---------------------------------------------------------------------------
__global__ void __launch_bounds__(THREADS, 1)
scan_kernel(const float* __restrict__ s_g)
{
    const int bh  = blockIdx.x >> 3;
    const int sli = blockIdx.x & 7;
    const int h   = bh & (H_ - 1);
    const float bd = expf(-s_g[h] * (float)CHK);
    const int tid = threadIdx.x;

    int u0 = tid,       d0 = u0 >> 2, q0 = u0 & 3;
    int u1 = tid + 256, d1 = u1 >> 2, q1 = u1 & 3;
    const int off0 = d0 * 32 + sli * 4 + q0;
    const int off1 = d1 * 32 + sli * 4 + q1;

    float4* base = reinterpret_cast<float4*>(g_states) + (size_t)bh * NBLK * (D_ * D_ / 4);
    float4 r0 = make_float4(0.f, 0.f, 0.f, 0.f), r1 = r0;
    for (int cc = 0; cc < NBLK; cc++) {
        float4* p = base + (size_t)cc * (D_ * D_ / 4);
        float4 t0 = p[off0], t1 = p[off1];
        p[off0] = r0;  p[off1] = r1;
        r0.x = bd * r0.x + t0.x;  r0.y = bd * r0.y + t0.y;
        r0.z = bd * r0.z + t0.z;  r0.w = bd * r0.w + t0.w;
        r1.x = bd * r1.x + t1.x;  r1.y = bd * r1.y + t1.y;
        r1.z = bd * r1.z + t1.z;  r1.w = bd * r1.w + t1.w;
    }
}

// ---------------------------------------------------------------------------
// Kernel 3: per (b,h,chunk):
//   GEMM1 (stream d): sc[t][s] = mask(t>=s) * exp(-sl(t-s)) * (q . k)
//   GEMM2 (stream d): o  = exp(-sl t) * (q @ S)   (S stored [e][d])
//   GEMM3 (stream s): o += sc @ v                 (v natural [s][e] -> T-chunk)
// ---------------------------------------------------------------------------
__global__ void __launch_bounds__(THREADS, 2)
out_kernel(const float* __restrict__ q_g, const float* __restrict__ k_g,
           const float* __restrict__ v_g, const float* __restrict__ s_g,
           float* __restrict__ o_g)
{
    extern __shared__ float sm[];
    float* tab  = sm + OF_TAB;
    float* bufS = sm + OF_SC;    // scores [t][s] K-major, stride STS_
    float* buf1 = sm + OF_S1;    // q chunks
    float* buf2 = sm + OF_S2;    // k/S chunks; phase3 v chunk

    const int tid = threadIdx.x;
    const int bhc = blockIdx.x;
    const int bh = bhc >> 5, h = bh & (H_ - 1);
    const float sl = s_g[h];
    const size_t cbase = ((size_t)bh * N_ + (size_t)(bhc & 31) * CHK) * D_;

    if (tid < 128) tab[tid] = expf(-sl * (float)tid);

    const int lane = tid & 31, wid = tid >> 5;
    const int g = lane >> 2, c = lane & 3;
    const int m0w = (wid & 3) * 32, n0w = (wid >> 2) * 64;

    float acc[2][8][4];
    zero_acc(acc);

    // ---- GEMM1: scores = q . k^T (stream k-dim = d) ----
    #pragma unroll 1
    for (int dc = 0; dc < 4; dc++) {
        load_kchunk(q_g + cbase, dc, buf1);
        load_kchunk(k_g + cbase, dc, buf2);
        __syncthreads();
        gemm_chunk_KK(buf1, buf2, acc, m0w, n0w, g, c);
        __syncthreads();
    }

    // transform -> bufS (mask + decay + tf32), zero acc
    #pragma unroll
    for (int mt = 0; mt < 2; mt++) {
        int t0 = m0w + mt * 16 + g, t1 = t0 + 8;
        #pragma unroll
        for (int nt = 0; nt < 8; nt++) {
            int s0 = n0w + nt * 8 + 2 * c;
            float w00 = (t0 >= s0)     ? acc[mt][nt][0] * tab[t0 - s0]     : 0.f;
            float w01 = (t0 >= s0 + 1) ? acc[mt][nt][1] * tab[t0 - s0 - 1] : 0.f;
            float w10 = (t1 >= s0)     ? acc[mt][nt][2] * tab[t1 - s0]     : 0.f;
            float w11 = (t1 >= s0 + 1) ? acc[mt][nt][3] * tab[t1 - s0 - 1] : 0.f;
            bufS[t0 * STS_ + s0]     = __uint_as_float(f2tf(w00));
            bufS[t0 * STS_ + s0 + 1] = __uint_as_float(f2tf(w01));
            bufS[t1 * STS_ + s0]     = __uint_as_float(f2tf(w10));
            bufS[t1 * STS_ + s0 + 1] = __uint_as_float(f2tf(w11));
            acc[mt][nt][0] = acc[mt][nt][1] = acc[mt][nt][2] = acc[mt][nt][3] = 0.f;
        }
    }

    // ---- GEMM2: inter = q @ S (stream k-dim = d; S[e][d]: n=e, k=d) ----
    const float* Sp = g_states + (size_t)bhc * D_ * D_;
    #pragma unroll 1
    for (int dc = 0; dc < 4; dc++) {
        load_kchunk(q_g + cbase, dc, buf1);
        load_kchunk(Sp, dc, buf2);
        __syncthreads();
        gemm_chunk_KK(buf1, buf2, acc, m0w, n0w, g, c);
        __syncthreads();
    }

    // scale inter rows by exp(-sl*t)
    #pragma unroll
    for (int mt = 0; mt < 2; mt++) {
        float f0 = tab[m0w + mt * 16 + g];
        float f1 = tab[m0w + mt * 16 + g + 8];
        #pragma unroll
        for (int nt = 0; nt < 8; nt++) {
            acc[mt][nt][0] *= f0;  acc[mt][nt][1] *= f0;
            acc[mt][nt][2] *= f1;  acc[mt][nt][3] *= f1;
        }
    }

    // ---- GEMM3: o += sc @ v (stream k-dim = s; v natural [s][e] chunks) ----
    #pragma unroll 1
    for (int sc = 0; sc < 4; sc++) {
        load_tchunk(v_g + cbase, sc, buf2, nullptr);
        __syncthreads();
        gemm_chunk_ST(bufS, buf2, sc * 32, acc, m0w, n0w, g, c);
        __syncthreads();
    }

    float* oc = o_g + cbase;
    #pragma unroll
    for (int mt = 0; mt < 2; mt++) {
        int r0 = m0w + mt * 16 + g;
        #pragma unroll
        for (int nt = 0; nt < 8; nt++) {
            int col = n0w + nt * 8 + 2 * c;
            *reinterpret_cast<float2*>(oc + r0 * 128 + col) =
                make_float2(acc[mt][nt][0], acc[mt][nt][1]);
            *reinterpret_cast<float2*>(oc + (r0 + 8) * 128 + col) =
                make_float2(acc[mt][nt][2], acc[mt][nt][3]);
        }
    }
}

// ---------------------------------------------------------------------------
extern "C" void kernel_launch(void* const* d_in, const int* in_sizes, int n_in,
                              void* d_out, int out_size)
{
    const float* q = (const float*)d_in[0];
    const float* k = (const float*)d_in[1];
    const float* v = (const float*)d_in[2];
    const float* s = (const float*)d_in[3];
    float* o = (float*)d_out;

    cudaFuncSetAttribute(kdv_kernel, cudaFuncAttributeMaxDynamicSharedMemorySize, SMEM_KDV);
    cudaFuncSetAttribute(out_kernel, cudaFuncAttributeMaxDynamicSharedMemorySize, SMEM_OUT);

    kdv_kernel<<<NCTA, THREADS, SMEM_KDV>>>(k, v, s);
    scan_kernel<<<BHc * 8, THREADS>>>(s);
    out_kernel<<<NCTA, THREADS, SMEM_OUT>>>(q, k, v, s, o);
}